// round 11
// baseline (speedup 1.0000x reference)
#include <cuda_runtime.h>

#define BATCH    16
#define NTUP     65536
#define IN_SIZE  4096
#define OUT_SIZE 4096
#define TPB      512
#define CPB      37                      // CTAs per batch
#define GRID_MAIN (BATCH * CPB)          // 592 = 148 SMs x 4 CTAs: one wave

__global__ __launch_bounds__(TPB, 4)
void hyper_main_kernel(const float*  __restrict__ x,
                       const float2* __restrict__ means,
                       const float*  __restrict__ sigmas,
                       const float*  __restrict__ values,
                       const float4* __restrict__ noise,
                       const float*  __restrict__ bias,
                       float* __restrict__ y) {
    __shared__ float sx[IN_SIZE];
    __shared__ float sy[OUT_SIZE];   // per-CTA private accumulator

    const int b = blockIdx.x & 15;   // batch
    const int r = blockIdx.x >> 4;   // rank within batch (0..36)

    // stage x[b] into shared + zero the private accumulator
    {
        const float4* xb4 = reinterpret_cast<const float4*>(x + b * IN_SIZE);
        float4* sx4 = reinterpret_cast<float4*>(sx);
        float4* sy4 = reinterpret_cast<float4*>(sy);
        const float4 z = make_float4(0.f, 0.f, 0.f, 0.f);
        #pragma unroll
        for (int i = threadIdx.x; i < IN_SIZE / 4; i += TPB) {
            sx4[i] = xb4[i];
            sy4[i] = z;
        }
    }
    __syncthreads();

    const int bn0 = b * NTUP;

    for (int n = r * TPB + threadIdx.x; n < NTUP; n += CPB * TPB) {
        const int bn = bn0 + n;

        const float2 mu  = means[bn];
        const float  sg  = sigmas[bn];
        const float  val = values[bn];

        int   oi[8];
        float c[8];          // unscaled contribution p[d] * sx[ii[d]]
        float psum = 0.0f;

        // two phases of 8 noise floats each: noise regs die between phases,
        // keeping peak live state ~ oi[8] + c[8]
        #pragma unroll
        for (int half = 0; half < 2; half++) {
            const float4 na = noise[bn * 4 + 2 * half + 0];
            const float4 nb = noise[bn * 4 + 2 * half + 1];
            const float nr[8] = { na.x, na.y, na.z, na.w,
                                  nb.x, nb.y, nb.z, nb.w };
            #pragma unroll
            for (int d = 0; d < 4; d++) {
                const float a0 = nr[2 * d + 0];
                const float a1 = nr[2 * d + 1];
                // sigma and the 2*pi*s2 denominator cancel in the
                // D-normalization: p depends only on the noise.
                const float p = __expf(-0.5f * (a0 * a0 + a1 * a1));
                psum += p;
                const float s0 = fmaf(a0, sg, mu.x);
                const float s1 = fmaf(a1, sg, mu.y);
                float f0 = rintf(s0);   // round-half-even == jnp.round
                float f1 = rintf(s1);
                f0 = fminf(fmaxf(f0, 0.0f), (float)(OUT_SIZE - 1));
                f1 = fminf(fmaxf(f1, 0.0f), (float)(IN_SIZE - 1));
                oi[4 * half + d] = (int)f0;
                c[4 * half + d]  = p * sx[(int)f1];
            }
        }

        const float scale = __fdividef(val, psum);

        // full 8-way merge by output row (scale factors out, applied at the
        // atomic). killed slot => oi=-1.
        #pragma unroll
        for (int d = 1; d < 8; d++) {
            const float cd = c[d];
            bool merged = false;
            #pragma unroll
            for (int j = 0; j < d; j++) {
                const bool eq = (!merged) && (oi[d] == oi[j]);
                if (eq) c[j] += cd;
                merged = merged || eq;
            }
            if (merged) oi[d] = -1;
        }

        #pragma unroll
        for (int d = 0; d < 8; d++) {
            if (oi[d] >= 0)
                atomicAdd(&sy[oi[d]], scale * c[d]);
        }
    }

    __syncthreads();

    // coalesced, vectorized flush; rank-0 CTA also injects the bias
    {
        const float4* sy4 = reinterpret_cast<const float4*>(sy);
        const float4* bias4 = reinterpret_cast<const float4*>(bias);
        float4* yb4 = reinterpret_cast<float4*>(y + b * OUT_SIZE);
        #pragma unroll
        for (int i = threadIdx.x; i < OUT_SIZE / 4; i += TPB) {
            float4 v = sy4[i];
            if (r == 0) {
                const float4 bv = bias4[i];
                v.x += bv.x; v.y += bv.y; v.z += bv.z; v.w += bv.w;
            }
            asm volatile("red.global.add.v4.f32 [%0], {%1, %2, %3, %4};"
                         :: "l"(yb4 + i), "f"(v.x), "f"(v.y), "f"(v.z), "f"(v.w)
                         : "memory");
        }
    }
}

extern "C" void kernel_launch(void* const* d_in, const int* in_sizes, int n_in,
                              void* d_out, int out_size) {
    const float*  x      = (const float*) d_in[0];  // [16, 4096]
    const float2* means  = (const float2*)d_in[1];  // [16, 65536, 2]
    const float*  sigmas = (const float*) d_in[2];  // [16, 65536]
    const float*  values = (const float*) d_in[3];  // [16, 65536]
    const float*  bias   = (const float*) d_in[4];  // [4096]
    const float4* noise  = (const float4*)d_in[5];  // [16, 65536, 8, 2]
    float* y = (float*)d_out;                       // [16, 4096]

    // zero the (poisoned) output; bias is added by the rank-0 CTA's flush
    cudaMemsetAsync(y, 0, (size_t)BATCH * OUT_SIZE * sizeof(float));

    hyper_main_kernel<<<GRID_MAIN, TPB>>>(x, means, sigmas, values, noise,
                                          bias, y);
}

// round 12
// speedup vs baseline: 1.2269x; 1.2269x over previous
#include <cuda_runtime.h>

#define BATCH    16
#define NTUP     65536
#define IN_SIZE  4096
#define OUT_SIZE 4096
#define TPB      512
#define CPB      37                      // CTAs per batch
#define GRID_MAIN (BATCH * CPB)          // 592 = 148 SMs x 4 CTAs: one wave

__global__ __launch_bounds__(TPB, 4)
void hyper_main_kernel(const float*  __restrict__ x,
                       const float2* __restrict__ means,
                       const float*  __restrict__ sigmas,
                       const float*  __restrict__ values,
                       const float4* __restrict__ noise,
                       const float*  __restrict__ bias,
                       float* __restrict__ y) {
    __shared__ float sx[IN_SIZE];
    __shared__ float sy[OUT_SIZE];   // per-CTA private accumulator

    const int b = blockIdx.x & 15;   // batch
    const int r = blockIdx.x >> 4;   // rank within batch (0..36)

    // stage x[b] into shared + zero the private accumulator
    {
        const float4* xb4 = reinterpret_cast<const float4*>(x + b * IN_SIZE);
        float4* sx4 = reinterpret_cast<float4*>(sx);
        float4* sy4 = reinterpret_cast<float4*>(sy);
        const float4 z = make_float4(0.f, 0.f, 0.f, 0.f);
        #pragma unroll
        for (int i = threadIdx.x; i < IN_SIZE / 4; i += TPB) {
            sx4[i] = xb4[i];
            sy4[i] = z;
        }
    }
    __syncthreads();

    // two adjacent lanes share one tuple; each lane owns 4 of the 8 samples
    const int h      = threadIdx.x & 1;          // half selector
    const int bn0    = b * NTUP;
    const int stride = CPB * (TPB / 2);

    for (int t = r * (TPB / 2) + (threadIdx.x >> 1); t < NTUP; t += stride) {
        const int bn = bn0 + t;

        const float2 mu  = means[bn];    // pair-duplicated, sector-shared
        const float  sg  = sigmas[bn];
        const float  val = values[bn];

        // this lane's 8 noise floats (consecutive tids -> contiguous float4s)
        const float4 nza = noise[bn * 4 + 2 * h + 0];
        const float4 nzb = noise[bn * 4 + 2 * h + 1];
        const float nr[8] = { nza.x, nza.y, nza.z, nza.w,
                              nzb.x, nzb.y, nzb.z, nzb.w };

        // probs: sigma and the 2*pi*s2 denominator cancel in the
        // D-normalization, so probs depend only on the noise.
        float p[4];
        float psum = 0.0f;
        #pragma unroll
        for (int d = 0; d < 4; d++) {
            const float a = nr[2 * d + 0];
            const float c = nr[2 * d + 1];
            p[d] = __expf(-0.5f * (a * a + c * c));
            psum += p[d];
        }
        // combine the two half-sums across the lane pair
        psum += __shfl_xor_sync(0xffffffffu, psum, 1);
        const float scale = __fdividef(val, psum);

        // 4 samples: address math + gather
        int   oi[4];
        float contrib[4];
        #pragma unroll
        for (int d = 0; d < 4; d++) {
            const float s0 = fmaf(nr[2 * d + 0], sg, mu.x);
            const float s1 = fmaf(nr[2 * d + 1], sg, mu.y);
            float f0 = rintf(s0);   // round-half-even == jnp.round
            float f1 = rintf(s1);
            f0 = fminf(fmaxf(f0, 0.0f), (float)(OUT_SIZE - 1));
            f1 = fminf(fmaxf(f1, 0.0f), (float)(IN_SIZE - 1));
            oi[d] = (int)f0;
            contrib[d] = (scale * p[d]) * sx[(int)f1];
        }

        // merge samples sharing an output row (within this lane's half)
        #pragma unroll
        for (int d = 1; d < 4; d++) {
            const float cd = contrib[d];
            bool merged = false;
            #pragma unroll
            for (int j = 0; j < d; j++) {
                const bool eq = (!merged) && (oi[d] == oi[j]);
                if (eq) contrib[j] += cd;
                merged = merged || eq;
            }
            if (merged) oi[d] = -1;
        }

        #pragma unroll
        for (int d = 0; d < 4; d++) {
            if (oi[d] >= 0)
                atomicAdd(&sy[oi[d]], contrib[d]);
        }
    }

    __syncthreads();

    // coalesced, vectorized flush; rank-0 CTA also injects the bias
    {
        const float4* sy4 = reinterpret_cast<const float4*>(sy);
        const float4* bias4 = reinterpret_cast<const float4*>(bias);
        float4* yb4 = reinterpret_cast<float4*>(y + b * OUT_SIZE);
        #pragma unroll
        for (int i = threadIdx.x; i < OUT_SIZE / 4; i += TPB) {
            float4 v = sy4[i];
            if (r == 0) {
                const float4 bv = bias4[i];
                v.x += bv.x; v.y += bv.y; v.z += bv.z; v.w += bv.w;
            }
            asm volatile("red.global.add.v4.f32 [%0], {%1, %2, %3, %4};"
                         :: "l"(yb4 + i), "f"(v.x), "f"(v.y), "f"(v.z), "f"(v.w)
                         : "memory");
        }
    }
}

extern "C" void kernel_launch(void* const* d_in, const int* in_sizes, int n_in,
                              void* d_out, int out_size) {
    const float*  x      = (const float*) d_in[0];  // [16, 4096]
    const float2* means  = (const float2*)d_in[1];  // [16, 65536, 2]
    const float*  sigmas = (const float*) d_in[2];  // [16, 65536]
    const float*  values = (const float*) d_in[3];  // [16, 65536]
    const float*  bias   = (const float*) d_in[4];  // [4096]
    const float4* noise  = (const float4*)d_in[5];  // [16, 65536, 8, 2]
    float* y = (float*)d_out;                       // [16, 4096]

    // zero the (poisoned) output; bias is added by the rank-0 CTAs' flush
    cudaMemsetAsync(y, 0, (size_t)BATCH * OUT_SIZE * sizeof(float));

    hyper_main_kernel<<<GRID_MAIN, TPB>>>(x, means, sigmas, values, noise,
                                          bias, y);
}